// round 14
// baseline (speedup 1.0000x reference)
#include <cuda_runtime.h>
#include <cuda_fp16.h>
#include <cstdint>

// ============================================================================
// FirUpsample2D, two-stage minimal-FLOP formulation (single stream).
// Stage 1 (tensor): y = convT(x, w, up=2, pad=2) as 4 parity-plane convs
//   (K = ntaps*256), y written FP16 into HALO-PADDED planes
//   g_Yp[n][plane][oc][68 x 72], interior cell (b,c) at (b+1, c+2).
//   Halo never written; __device__ globals zero-initialized -> zeros.
//   Conv CTA: 256 threads, M=128 (one oc-half) x N=128 pos, 2 CTAs/SM.
// Stage 2 (memory): parity blend [.25,.75]^2 + bias; thread = 2 rows x 8 cols.
// ============================================================================

#define CIN 256
#define OCH 256

__device__ __align__(16) __half g_W2[4 * 2 * 16 * 8192];
__device__ __align__(16) uint4 g_X8[8 * 32 * 4096];
__device__ __align__(16) __half g_Yp[8 * 4 * 256 * 4896];

__device__ __forceinline__ uint32_t swz(uint32_t o) { return o ^ ((o >> 3) & 0x70); }

__device__ __forceinline__ uint32_t smem_u32(const void* p) {
    uint32_t a;
    asm("{ .reg .u64 t; cvta.to.shared.u64 t, %1; cvt.u32.u64 %0, t; }" : "=r"(a) : "l"(p));
    return a;
}

#define CP16(d, s) asm volatile("cp.async.cg.shared.global [%0], [%1], 16;" :: "r"(d), "l"(s) : "memory")
#define CP16Z(d, s, z) asm volatile("cp.async.cg.shared.global [%0], [%1], 16, %2;" :: "r"(d), "l"(s), "r"(z) : "memory")
#define CP_COMMIT() asm volatile("cp.async.commit_group;" ::: "memory")
#define CP_WAIT1() asm volatile("cp.async.wait_group 1;" ::: "memory")
#define CP_WAIT0() asm volatile("cp.async.wait_group 0;" ::: "memory")

#define LDSM4(r, a) asm volatile( \
    "ldmatrix.sync.aligned.m8n8.x4.shared.b16 {%0,%1,%2,%3}, [%4];" \
    : "=r"((r)[0]), "=r"((r)[1]), "=r"((r)[2]), "=r"((r)[3]) : "r"(a))
#define LDSM2(r, a) asm volatile( \
    "ldmatrix.sync.aligned.m8n8.x2.shared.b16 {%0,%1}, [%2];" \
    : "=r"((r)[0]), "=r"((r)[1]) : "r"(a))

#define MMA(c, a, b) asm volatile( \
    "mma.sync.aligned.m16n8k16.row.col.f32.f16.f16.f32 " \
    "{%0,%1,%2,%3},{%4,%5,%6,%7},{%8,%9},{%0,%1,%2,%3};" \
    : "+f"((c)[0]), "+f"((c)[1]), "+f"((c)[2]), "+f"((c)[3]) \
    : "r"((a)[0]), "r"((a)[1]), "r"((a)[2]), "r"((a)[3]), "r"((b)[0]), "r"((b)[1]))

// ---------------------------------------------------------------------------
// fused prep: blocks [0,2048) pack x -> c8 fp16; blocks [2048,2176) build
// per-plane fp16 weight images (2 oc per block).   (validated R13)
// ---------------------------------------------------------------------------
__global__ __launch_bounds__(512) void prep_fused_kernel(
    const float* __restrict__ x, const float* __restrict__ weight)
{
    if (blockIdx.x < 2048) {
        int idx = blockIdx.x * 512 + threadIdx.x;
        int hw = idx & 4095;
        int c8 = (idx >> 12) & 31;
        int n  = idx >> 17;
        const float* px = x + ((size_t)n * CIN + c8 * 8) * 4096 + hw;
        ushort h[8];
#pragma unroll
        for (int i = 0; i < 8; i++)
            h[i] = __half_as_ushort(__float2half_rn(px[i * 4096]));
        uint4 v;
        v.x = (uint32_t)h[0] | ((uint32_t)h[1] << 16);
        v.y = (uint32_t)h[2] | ((uint32_t)h[3] << 16);
        v.z = (uint32_t)h[4] | ((uint32_t)h[5] << 16);
        v.w = (uint32_t)h[6] | ((uint32_t)h[7] << 16);
        g_X8[idx] = v;
    } else {
        int b = blockIdx.x - 2048;             // 0..127
        int oc = b * 2 + (threadIdx.x >> 8);
        int ch = threadIdx.x & 255;
        float wv[3][3];
#pragma unroll
        for (int u = 0; u < 3; u++)
#pragma unroll
            for (int v = 0; v < 3; v++)
                wv[u][v] = weight[((oc * CIN + ch) * 3 + u) * 3 + v];

        int octile = oc >> 7, row = oc & 127;
        int q = ch >> 6, k = ch & 63;

        auto st = [&](int plane, int t, int u, int v) {
            int kc = t * 4 + q;
            size_t off = ((size_t)((plane * 2 + octile) * 16 + kc)) * 8192
                       + (size_t)row * 64 + k;
            g_W2[off] = __float2half_rn(wv[u][v]);
        };
        st(0, 0, 0, 0); st(0, 1, 0, 2); st(0, 2, 2, 0); st(0, 3, 2, 2);
        st(1, 0, 0, 1); st(1, 1, 2, 1);
        st(2, 0, 1, 0); st(2, 1, 1, 2);
        st(3, 0, 1, 1);
    }
}

// ---------------------------------------------------------------------------
// Stage 1: grid (68 = tile*2+octile, 8 n, 4 planes), 256 threads, 64KB smem,
// 2 CTAs/SM. CTA: M=128 oc x N=128 positions, K-stage = one 64-chunk.
// Warp layout: wm = warp&1 (M64), wn = warp>>1 (N32). MMA maps validated.
// ---------------------------------------------------------------------------
__global__ __launch_bounds__(256, 2) void conv_s1_kernel() {
    const int plane = blockIdx.z;
    const int n = blockIdx.y;
    const int bx = blockIdx.x;
    const int tile = bx >> 1;
    const int octile = bx & 1;

    const int R = 65 - (plane >> 1);
    const int C = 65 - (plane & 1);
    const int npos = R * C;
    if (tile * 128 >= npos) return;
    const int nst = (plane == 0) ? 16 : ((plane == 3) ? 4 : 8);

    extern __shared__ char smem[];
    const uint32_t sb = smem_u32(smem);
    const int tid = threadIdx.x;
    const int warp = tid >> 5, lane = tid & 31;
    const int wm = warp & 1, wn = warp >> 1;

    float acc[4][4][4];
#pragma unroll
    for (int mf = 0; mf < 4; mf++)
#pragma unroll
        for (int nf = 0; nf < 4; nf++)
#pragma unroll
            for (int i = 0; i < 4; i++) acc[mf][nf][i] = 0.0f;

    // B prefetch geometry: 2 threads per position (hfB = upper/lower 32 ch)
    const int posT = tid & 127;
    const int hfB = tid >> 7;
    const int pos = tile * 128 + posT;
    int bT, cT;
    if ((plane & 1) == 0) { bT = (int)(((unsigned)pos * 16133u) >> 20); cT = pos - bT * 65; }
    else                  { bT = pos >> 6; cT = pos & 63; }
    const int posOK = pos < npos;

    // ldmatrix geometry (validated mapping; wm now 1 bit)
    const int rowA0 = wm * 64 + (lane & 7) + ((lane >> 3) & 1) * 8;
    const int kbA = ((lane >> 4) & 1) * 16;
    const int rowB0 = wn * 32 + (lane & 7);
    const int kbB = ((lane >> 3) & 1) * 16;

#define PREFETCH(st, s) do {                                                        \
    uint32_t stg = sb + (uint32_t)(s) * 32768u;                                     \
    /* A: one 16KB tile (this octile, chunk kc=st): 4 float4/thread */              \
    {                                                                               \
        const unsigned char* srcA = (const unsigned char*)g_W2                      \
            + ((size_t)((plane * 2 + octile) * 16 + (st))) * 16384u;                \
        _Pragma("unroll")                                                           \
        for (int j = 0; j < 4; j++) {                                               \
            uint32_t idx = (uint32_t)(j * 256 + tid);                               \
            CP16(stg + swz(idx * 16u), srcA + idx * 16u);                           \
        }                                                                           \
    }                                                                               \
    /* B: 128 pos x 64 ch; per thread 4 CP16Z (32 ch half) */                       \
    {                                                                               \
        int t = (st) >> 2, q = (st) & 3;                                            \
        int gh, gw;                                                                 \
        if (plane == 0)      { gh = bT - 1 + (t >> 1); gw = cT - 1 + (t & 1); }     \
        else if (plane == 1) { gh = bT - 1 + t;        gw = cT; }                   \
        else if (plane == 2) { gh = bT;                gw = cT - 1 + t; }           \
        else                 { gh = bT;                gw = cT; }                   \
        int inb = ((unsigned)gh < 64u && (unsigned)gw < 64u && posOK) ? 16 : 0;     \
        uint32_t gidx = (uint32_t)((n * 32 + q * 8 + hfB * 4) * 4096)               \
                        + (inb ? (uint32_t)(gh * 64 + gw) : 0u);                    \
        uint32_t boff = (uint32_t)posT * 128u + (uint32_t)hfB * 64u;                \
        _Pragma("unroll")                                                           \
        for (int i = 0; i < 4; i++)                                                 \
            CP16Z(stg + 16384u + swz(boff + (uint32_t)i * 16u),                     \
                  g_X8 + gidx + i * 4096, inb);                                     \
    }                                                                               \
} while (0)

    PREFETCH(0, 0);
    CP_COMMIT();

    for (int st = 0; st < nst; st++) {
        const int s = st & 1;
        if (st + 1 < nst) {
            PREFETCH(st + 1, s ^ 1);
            CP_COMMIT();
            CP_WAIT1();
        } else {
            CP_WAIT0();
        }
        __syncthreads();

        const uint32_t A0 = sb + (uint32_t)s * 32768u;
        const uint32_t B0 = A0 + 16384u;
#pragma unroll
        for (int ks = 0; ks < 4; ks++) {
            uint32_t a[4][4], b[4][2];
#pragma unroll
            for (int mf = 0; mf < 4; mf++) {
                uint32_t ao = swz((uint32_t)(rowA0 + mf * 16) * 128u
                                  + (uint32_t)(ks * 32 + kbA));
                LDSM4(a[mf], A0 + ao);
            }
#pragma unroll
            for (int nf = 0; nf < 4; nf++) {
                uint32_t bo = swz((uint32_t)(rowB0 + nf * 8) * 128u
                                  + (uint32_t)(ks * 32 + kbB));
                LDSM2(b[nf], B0 + bo);
            }
#pragma unroll
            for (int mf = 0; mf < 4; mf++)
#pragma unroll
                for (int nf = 0; nf < 4; nf++)
                    MMA(acc[mf][nf], a[mf], b[nf]);
        }
        __syncthreads();
    }

    // ---- epilogue: write fp16 y into padded slices (halo untouched = zero)
    const int g = lane >> 2, tq = lane & 3;
    __half* ybase = g_Yp + (size_t)((n * 4 + plane) * 256) * 4896;
#pragma unroll
    for (int mf = 0; mf < 4; mf++) {
#pragma unroll
        for (int nf = 0; nf < 4; nf++) {
            int pos0 = tile * 128 + wn * 32 + nf * 8 + tq * 2;
            if (pos0 >= npos) continue;
            int oc0 = octile * 128 + wm * 64 + mf * 16 + g;
            __half* s0 = ybase + (size_t)oc0 * 4896;
            __half* s1 = ybase + (size_t)(oc0 + 8) * 4896;
            int b, c;
            if ((plane & 1) == 0) { b = (int)(((unsigned)pos0 * 16133u) >> 20); c = pos0 - b * 65; }
            else                  { b = pos0 >> 6; c = pos0 & 63; }
            uint32_t o0 = (uint32_t)(b + 1) * 72u + (uint32_t)(c + 2);
            bool pair = (pos0 + 1 < npos);
            __half h0 = __float2half_rn(acc[mf][nf][0]);
            __half h1 = __float2half_rn(acc[mf][nf][1]);
            __half h2 = __float2half_rn(acc[mf][nf][2]);
            __half h3 = __float2half_rn(acc[mf][nf][3]);
            if (pair && c < C - 1) {
                if ((c & 1) == 0) {
                    *(__half2*)(s0 + o0) = __halves2half2(h0, h1);
                    *(__half2*)(s1 + o0) = __halves2half2(h2, h3);
                } else {
                    s0[o0] = h0; s0[o0 + 1] = h1;
                    s1[o0] = h2; s1[o0 + 1] = h3;
                }
            } else {
                s0[o0] = h0;
                s1[o0] = h2;
                if (pair) {          // row straddle (odd-width plane, c == C-1)
                    uint32_t o1 = (uint32_t)(b + 2) * 72u + 2u;
                    s0[o1] = h1;
                    s1[o1] = h3;
                }
            }
        }
    }
}

// ---------------------------------------------------------------------------
// Stage 2: FIR parity blend + bias. Thread -> 2 rows x 8 out cols (two k-pairs,
// k0 = 4*kg even => all half2 loads aligned). grid (256 oc, 8 n, 4), 256 thr.
// (validated R13)
// ---------------------------------------------------------------------------
__global__ __launch_bounds__(256) void blur_kernel(
    const float* __restrict__ bias, float* __restrict__ out)
{
    const int oc = blockIdx.x, n = blockIdx.y, rg = blockIdx.z;
    const int tid = threadIdx.x;
    const __half* EEp = g_Yp + ((size_t)(n * 4 + 0) * 256 + oc) * 4896;
    const __half* EOp = g_Yp + ((size_t)(n * 4 + 1) * 256 + oc) * 4896;
    const __half* OEp = g_Yp + ((size_t)(n * 4 + 2) * 256 + oc) * 4896;
    const __half* OOp = g_Yp + ((size_t)(n * 4 + 3) * 256 + oc) * 4896;
    const float bv = bias[oc];
    float* obase = out + (size_t)(n * 256 + oc) * 16384;

    const float A = 0.25f, B = 0.75f;
    int id = rg * 256 + tid;              // 0..1023
    int m = id >> 4, kg = id & 15;
    int k0 = kg * 4;                      // even y-column base, 2 pairs

    float rowE[2][8], rowO[3][8];
#pragma unroll
    for (int i = 0; i < 2; i++) {
        const __half2* eeP = (const __half2*)(EEp + (m + 1 + i) * 72 + k0 + 2);
        const __half2* eoP = (const __half2*)(EOp + (m + 1 + i) * 72 + k0);
        float2 a0 = __half22float2(eeP[0]);
        float2 a1 = __half22float2(eeP[1]);
        float2 a2 = __half22float2(eeP[2]);
        float2 c0 = __half22float2(eoP[0]);
        float2 c1 = __half22float2(eoP[1]);
        float2 c2 = __half22float2(eoP[2]);
        float2 c3 = __half22float2(eoP[3]);
        float e_[6] = {a0.x, a0.y, a1.x, a1.y, a2.x, a2.y};
        float f_[8] = {c0.x, c0.y, c1.x, c1.y, c2.x, c2.y, c3.x, c3.y};
#pragma unroll
        for (int j = 0; j < 2; j++) {
            rowE[i][4*j+0] = B * e_[2*j]   + A * e_[2*j+1] + A * f_[2*j+1] + B * f_[2*j+2];
            rowE[i][4*j+1] = A * e_[2*j]   + B * e_[2*j+1] + B * f_[2*j+2] + A * f_[2*j+3];
            rowE[i][4*j+2] = B * e_[2*j+1] + A * e_[2*j+2] + A * f_[2*j+2] + B * f_[2*j+3];
            rowE[i][4*j+3] = A * e_[2*j+1] + B * e_[2*j+2] + B * f_[2*j+3] + A * f_[2*j+4];
        }
    }
#pragma unroll
    for (int i = 0; i < 3; i++) {
        const __half2* oeP = (const __half2*)(OEp + (m + i) * 72 + k0 + 2);
        const __half2* ooP = (const __half2*)(OOp + (m + i) * 72 + k0);
        float2 a0 = __half22float2(oeP[0]);
        float2 a1 = __half22float2(oeP[1]);
        float2 a2 = __half22float2(oeP[2]);
        float2 c0 = __half22float2(ooP[0]);
        float2 c1 = __half22float2(ooP[1]);
        float2 c2 = __half22float2(ooP[2]);
        float2 c3 = __half22float2(ooP[3]);
        float e_[6] = {a0.x, a0.y, a1.x, a1.y, a2.x, a2.y};
        float f_[8] = {c0.x, c0.y, c1.x, c1.y, c2.x, c2.y, c3.x, c3.y};
#pragma unroll
        for (int j = 0; j < 2; j++) {
            rowO[i][4*j+0] = B * e_[2*j]   + A * e_[2*j+1] + A * f_[2*j+1] + B * f_[2*j+2];
            rowO[i][4*j+1] = A * e_[2*j]   + B * e_[2*j+1] + B * f_[2*j+2] + A * f_[2*j+3];
            rowO[i][4*j+2] = B * e_[2*j+1] + A * e_[2*j+2] + A * f_[2*j+2] + B * f_[2*j+3];
            rowO[i][4*j+3] = A * e_[2*j+1] + B * e_[2*j+2] + B * f_[2*j+3] + A * f_[2*j+4];
        }
    }

    float o0[8], o1[8];
#pragma unroll
    for (int c = 0; c < 8; c++) {
        o0[c] = B * rowE[0][c] + A * rowE[1][c] + A * rowO[0][c] + B * rowO[1][c] + bv;
        o1[c] = A * rowE[0][c] + B * rowE[1][c] + B * rowO[1][c] + A * rowO[2][c] + bv;
    }
    float* d0 = obase + (2 * m) * 128 + 2 * k0;
    float* d1 = obase + (2 * m + 1) * 128 + 2 * k0;
    *(float4*)(d0)     = make_float4(o0[0], o0[1], o0[2], o0[3]);
    *(float4*)(d0 + 4) = make_float4(o0[4], o0[5], o0[6], o0[7]);
    *(float4*)(d1)     = make_float4(o1[0], o1[1], o1[2], o1[3]);
    *(float4*)(d1 + 4) = make_float4(o1[4], o1[5], o1[6], o1[7]);
}

extern "C" void kernel_launch(void* const* d_in, const int* in_sizes, int n_in,
                              void* d_out, int out_size) {
    const float* hidden = (const float*)d_in[0];   // (8,256,64,64)
    const float* weight = (const float*)d_in[1];   // (256,256,3,3)
    const float* bias   = (const float*)d_in[2];   // (256,)
    float* out = (float*)d_out;                    // (8,256,128,128)

    cudaFuncSetAttribute(conv_s1_kernel,
                         cudaFuncAttributeMaxDynamicSharedMemorySize, 65536);

    prep_fused_kernel<<<2176, 512>>>(hidden, weight);
    conv_s1_kernel<<<dim3(68, 8, 4), 256, 65536>>>();
    blur_kernel<<<dim3(256, 8, 4), 256>>>(bias, out);
}

// round 15
// speedup vs baseline: 1.0654x; 1.0654x over previous
#include <cuda_runtime.h>
#include <cuda_fp16.h>
#include <cstdint>

// ============================================================================
// FirUpsample2D, two-stage minimal-FLOP formulation (single stream, R13 base).
// Stage 1 (tensor): y = convT(x, w, up=2, pad=2) as 4 parity-plane convs
//   (K = ntaps*256), y written FP16 into HALO-PADDED planes
//   g_Yp[n][plane][oc][68 x 72], interior cell (b,c) at (b+1, c+2).
//   Halo never written; __device__ globals zero-initialized -> zeros.
// Stage 2 (memory): parity blend [.25,.75]^2 + bias; thread = 2 rows x 8 cols.
// R15 delta vs R13: B fragments loaded via LDSM4 (nf-pairs), -25% shared ops.
// ============================================================================

#define CIN 256
#define OCH 256

__device__ __align__(16) __half g_W2[4 * 2 * 16 * 8192];
__device__ __align__(16) uint4 g_X8[8 * 32 * 4096];
__device__ __align__(16) __half g_Yp[8 * 4 * 256 * 4896];

__device__ __forceinline__ uint32_t swz(uint32_t o) { return o ^ ((o >> 3) & 0x70); }

__device__ __forceinline__ uint32_t smem_u32(const void* p) {
    uint32_t a;
    asm("{ .reg .u64 t; cvta.to.shared.u64 t, %1; cvt.u32.u64 %0, t; }" : "=r"(a) : "l"(p));
    return a;
}

#define CP16(d, s) asm volatile("cp.async.cg.shared.global [%0], [%1], 16;" :: "r"(d), "l"(s) : "memory")
#define CP16Z(d, s, z) asm volatile("cp.async.cg.shared.global [%0], [%1], 16, %2;" :: "r"(d), "l"(s), "r"(z) : "memory")
#define CP_COMMIT() asm volatile("cp.async.commit_group;" ::: "memory")
#define CP_WAIT1() asm volatile("cp.async.wait_group 1;" ::: "memory")
#define CP_WAIT0() asm volatile("cp.async.wait_group 0;" ::: "memory")

#define LDSM4(r, a) asm volatile( \
    "ldmatrix.sync.aligned.m8n8.x4.shared.b16 {%0,%1,%2,%3}, [%4];" \
    : "=r"((r)[0]), "=r"((r)[1]), "=r"((r)[2]), "=r"((r)[3]) : "r"(a))

#define MMA(c, a, b) asm volatile( \
    "mma.sync.aligned.m16n8k16.row.col.f32.f16.f16.f32 " \
    "{%0,%1,%2,%3},{%4,%5,%6,%7},{%8,%9},{%0,%1,%2,%3};" \
    : "+f"((c)[0]), "+f"((c)[1]), "+f"((c)[2]), "+f"((c)[3]) \
    : "r"((a)[0]), "r"((a)[1]), "r"((a)[2]), "r"((a)[3]), "r"((b)[0]), "r"((b)[1]))

// ---------------------------------------------------------------------------
// fused prep: blocks [0,2048) pack x -> c8 fp16; blocks [2048,2176) build
// per-plane fp16 weight images (2 oc per block).   (validated R13)
// ---------------------------------------------------------------------------
__global__ __launch_bounds__(512) void prep_fused_kernel(
    const float* __restrict__ x, const float* __restrict__ weight)
{
    if (blockIdx.x < 2048) {
        int idx = blockIdx.x * 512 + threadIdx.x;
        int hw = idx & 4095;
        int c8 = (idx >> 12) & 31;
        int n  = idx >> 17;
        const float* px = x + ((size_t)n * CIN + c8 * 8) * 4096 + hw;
        ushort h[8];
#pragma unroll
        for (int i = 0; i < 8; i++)
            h[i] = __half_as_ushort(__float2half_rn(px[i * 4096]));
        uint4 v;
        v.x = (uint32_t)h[0] | ((uint32_t)h[1] << 16);
        v.y = (uint32_t)h[2] | ((uint32_t)h[3] << 16);
        v.z = (uint32_t)h[4] | ((uint32_t)h[5] << 16);
        v.w = (uint32_t)h[6] | ((uint32_t)h[7] << 16);
        g_X8[idx] = v;
    } else {
        int b = blockIdx.x - 2048;             // 0..127
        int oc = b * 2 + (threadIdx.x >> 8);
        int ch = threadIdx.x & 255;
        float wv[3][3];
#pragma unroll
        for (int u = 0; u < 3; u++)
#pragma unroll
            for (int v = 0; v < 3; v++)
                wv[u][v] = weight[((oc * CIN + ch) * 3 + u) * 3 + v];

        int octile = oc >> 7, row = oc & 127;
        int q = ch >> 6, k = ch & 63;

        auto st = [&](int plane, int t, int u, int v) {
            int kc = t * 4 + q;
            size_t off = ((size_t)((plane * 2 + octile) * 16 + kc)) * 8192
                       + (size_t)row * 64 + k;
            g_W2[off] = __float2half_rn(wv[u][v]);
        };
        st(0, 0, 0, 0); st(0, 1, 0, 2); st(0, 2, 2, 0); st(0, 3, 2, 2);
        st(1, 0, 0, 1); st(1, 1, 2, 1);
        st(2, 0, 1, 0); st(2, 1, 1, 2);
        st(3, 0, 1, 1);
    }
}

// ---------------------------------------------------------------------------
// Stage 1: grid (34 tiles, 8 n, 4 planes), 512 threads, 192KB smem.
// CTA: M=256 oc x N=128 flat plane positions. MMA core validated (R6-R13);
// B loads fused to LDSM4 nf-pairs.
// ---------------------------------------------------------------------------
__global__ __launch_bounds__(512, 1) void conv_s1_kernel() {
    const int plane = blockIdx.z;
    const int n = blockIdx.y;
    const int tile = blockIdx.x;

    const int R = 65 - (plane >> 1);
    const int C = 65 - (plane & 1);
    const int npos = R * C;
    if (tile * 128 >= npos) return;
    const int nst = (plane == 0) ? 8 : ((plane == 3) ? 2 : 4);

    extern __shared__ char smem[];
    const uint32_t sb = smem_u32(smem);
    const int tid = threadIdx.x;
    const int warp = tid >> 5, lane = tid & 31;
    const int wm = warp & 3, wn = warp >> 2;

    float acc[4][4][4];
#pragma unroll
    for (int mf = 0; mf < 4; mf++)
#pragma unroll
        for (int nf = 0; nf < 4; nf++)
#pragma unroll
            for (int i = 0; i < 4; i++) acc[mf][nf][i] = 0.0f;

    // B prefetch geometry
    const int posT = tid & 127;
    const int selB = tid >> 7;
    const int kcuB = selB >> 1, hfB = selB & 1;
    const int pos = tile * 128 + posT;
    int bT, cT;
    if ((plane & 1) == 0) { bT = (int)(((unsigned)pos * 16133u) >> 20); cT = pos - bT * 65; }
    else                  { bT = pos >> 6; cT = pos & 63; }
    const int posOK = pos < npos;

    // ldmatrix geometry (validated A mapping; B re-derived for LDSM4 pairs)
    const int rowA0 = wm * 64 + (lane & 7) + ((lane >> 3) & 1) * 8;
    const int kbA = ((lane >> 4) & 1) * 16;
    // B LDSM4: lanes 0-7 -> (rowgrp 2p, k-lo), 8-15 -> (2p, k-hi),
    //          16-23 -> (2p+1, k-lo), 24-31 -> (2p+1, k-hi)
    const int rowB4 = wn * 32 + ((lane >> 4) & 1) * 8 + (lane & 7);
    const int kbB = ((lane >> 3) & 1) * 16;

#define PREFETCH(st, s) do {                                                        \
    uint32_t stg = sb + (uint32_t)(s) * 98304u;                                     \
    _Pragma("unroll")                                                               \
    for (int j = 0; j < 8; j++) {                                                   \
        uint32_t v = (uint32_t)(j * 512 + tid);                                     \
        uint32_t tile4 = v >> 10, idx = v & 1023;                                   \
        int kcu = tile4 >> 1, octile = tile4 & 1;                                   \
        const unsigned char* src = (const unsigned char*)g_W2                       \
            + ((size_t)((plane * 2 + octile) * 16 + (2 * (st) + kcu))) * 16384u     \
            + idx * 16u;                                                            \
        CP16(stg + tile4 * 16384u + swz(idx * 16u), src);                           \
    }                                                                               \
    {                                                                               \
        int kc = 2 * (st) + kcuB;                                                   \
        int t = kc >> 2, q = kc & 3;                                                \
        int gh, gw;                                                                 \
        if (plane == 0)      { gh = bT - 1 + (t >> 1); gw = cT - 1 + (t & 1); }     \
        else if (plane == 1) { gh = bT - 1 + t;        gw = cT; }                   \
        else if (plane == 2) { gh = bT;                gw = cT - 1 + t; }           \
        else                 { gh = bT;                gw = cT; }                   \
        int inb = ((unsigned)gh < 64u && (unsigned)gw < 64u && posOK) ? 16 : 0;     \
        uint32_t gidx = (uint32_t)((n * 32 + q * 8 + hfB * 4) * 4096)               \
                        + (inb ? (uint32_t)(gh * 64 + gw) : 0u);                    \
        uint32_t brow = stg + 65536u + (uint32_t)kcuB * 16384u;                     \
        uint32_t boff = (uint32_t)posT * 128u + (uint32_t)hfB * 64u;                \
        _Pragma("unroll")                                                           \
        for (int i = 0; i < 4; i++)                                                 \
            CP16Z(brow + swz(boff + (uint32_t)i * 16u),                             \
                  g_X8 + gidx + i * 4096, inb);                                     \
    }                                                                               \
} while (0)

    PREFETCH(0, 0);
    CP_COMMIT();

    for (int st = 0; st < nst; st++) {
        const int s = st & 1;
        if (st + 1 < nst) {
            PREFETCH(st + 1, s ^ 1);
            CP_COMMIT();
            CP_WAIT1();
        } else {
            CP_WAIT0();
        }
        __syncthreads();

        const uint32_t stg = sb + (uint32_t)s * 98304u;
#pragma unroll
        for (int kcu = 0; kcu < 2; kcu++) {
            const uint32_t A0 = stg + (uint32_t)kcu * 32768u;
            const uint32_t B0 = stg + 65536u + (uint32_t)kcu * 16384u;
#pragma unroll
            for (int ks = 0; ks < 4; ks++) {
                uint32_t a[4][4], b[4][2];
#pragma unroll
                for (int mf = 0; mf < 4; mf++) {
                    uint32_t ao = swz((uint32_t)(rowA0 + mf * 16) * 128u
                                      + (uint32_t)(ks * 32 + kbA));
                    LDSM4(a[mf], A0 + ao);
                }
#pragma unroll
                for (int p = 0; p < 2; p++) {
                    uint32_t tmp[4];
                    uint32_t bo = swz((uint32_t)(rowB4 + p * 16) * 128u
                                      + (uint32_t)(ks * 32 + kbB));
                    LDSM4(tmp, B0 + bo);
                    b[2 * p][0] = tmp[0]; b[2 * p][1] = tmp[1];
                    b[2 * p + 1][0] = tmp[2]; b[2 * p + 1][1] = tmp[3];
                }
#pragma unroll
                for (int mf = 0; mf < 4; mf++)
#pragma unroll
                    for (int nf = 0; nf < 4; nf++)
                        MMA(acc[mf][nf], a[mf], b[nf]);
            }
        }
        __syncthreads();
    }

    // ---- epilogue: write fp16 y into padded slices (halo untouched = zero)
    const int g = lane >> 2, tq = lane & 3;
    __half* ybase = g_Yp + (size_t)((n * 4 + plane) * 256) * 4896;
#pragma unroll
    for (int mf = 0; mf < 4; mf++) {
#pragma unroll
        for (int nf = 0; nf < 4; nf++) {
            int pos0 = tile * 128 + wn * 32 + nf * 8 + tq * 2;
            if (pos0 >= npos) continue;
            int oc0 = wm * 64 + mf * 16 + g;
            __half* s0 = ybase + (size_t)oc0 * 4896;
            __half* s1 = ybase + (size_t)(oc0 + 8) * 4896;
            int b, c;
            if ((plane & 1) == 0) { b = (int)(((unsigned)pos0 * 16133u) >> 20); c = pos0 - b * 65; }
            else                  { b = pos0 >> 6; c = pos0 & 63; }
            uint32_t o0 = (uint32_t)(b + 1) * 72u + (uint32_t)(c + 2);
            bool pair = (pos0 + 1 < npos);
            __half h0 = __float2half_rn(acc[mf][nf][0]);
            __half h1 = __float2half_rn(acc[mf][nf][1]);
            __half h2 = __float2half_rn(acc[mf][nf][2]);
            __half h3 = __float2half_rn(acc[mf][nf][3]);
            if (pair && c < C - 1) {
                if ((c & 1) == 0) {
                    *(__half2*)(s0 + o0) = __halves2half2(h0, h1);
                    *(__half2*)(s1 + o0) = __halves2half2(h2, h3);
                } else {
                    s0[o0] = h0; s0[o0 + 1] = h1;
                    s1[o0] = h2; s1[o0 + 1] = h3;
                }
            } else {
                s0[o0] = h0;
                s1[o0] = h2;
                if (pair) {          // row straddle (odd-width plane, c == C-1)
                    uint32_t o1 = (uint32_t)(b + 2) * 72u + 2u;
                    s0[o1] = h1;
                    s1[o1] = h3;
                }
            }
        }
    }
}

// ---------------------------------------------------------------------------
// Stage 2: FIR parity blend + bias. Thread -> 2 rows x 8 out cols (two k-pairs,
// k0 = 4*kg even => all half2 loads aligned). grid (256 oc, 8 n, 4), 256 thr.
// (validated R13)
// ---------------------------------------------------------------------------
__global__ __launch_bounds__(256) void blur_kernel(
    const float* __restrict__ bias, float* __restrict__ out)
{
    const int oc = blockIdx.x, n = blockIdx.y, rg = blockIdx.z;
    const int tid = threadIdx.x;
    const __half* EEp = g_Yp + ((size_t)(n * 4 + 0) * 256 + oc) * 4896;
    const __half* EOp = g_Yp + ((size_t)(n * 4 + 1) * 256 + oc) * 4896;
    const __half* OEp = g_Yp + ((size_t)(n * 4 + 2) * 256 + oc) * 4896;
    const __half* OOp = g_Yp + ((size_t)(n * 4 + 3) * 256 + oc) * 4896;
    const float bv = bias[oc];
    float* obase = out + (size_t)(n * 256 + oc) * 16384;

    const float A = 0.25f, B = 0.75f;
    int id = rg * 256 + tid;              // 0..1023
    int m = id >> 4, kg = id & 15;
    int k0 = kg * 4;                      // even y-column base, 2 pairs

    float rowE[2][8], rowO[3][8];
#pragma unroll
    for (int i = 0; i < 2; i++) {
        const __half2* eeP = (const __half2*)(EEp + (m + 1 + i) * 72 + k0 + 2);
        const __half2* eoP = (const __half2*)(EOp + (m + 1 + i) * 72 + k0);
        float2 a0 = __half22float2(eeP[0]);
        float2 a1 = __half22float2(eeP[1]);
        float2 a2 = __half22float2(eeP[2]);
        float2 c0 = __half22float2(eoP[0]);
        float2 c1 = __half22float2(eoP[1]);
        float2 c2 = __half22float2(eoP[2]);
        float2 c3 = __half22float2(eoP[3]);
        float e_[6] = {a0.x, a0.y, a1.x, a1.y, a2.x, a2.y};
        float f_[8] = {c0.x, c0.y, c1.x, c1.y, c2.x, c2.y, c3.x, c3.y};
#pragma unroll
        for (int j = 0; j < 2; j++) {
            rowE[i][4*j+0] = B * e_[2*j]   + A * e_[2*j+1] + A * f_[2*j+1] + B * f_[2*j+2];
            rowE[i][4*j+1] = A * e_[2*j]   + B * e_[2*j+1] + B * f_[2*j+2] + A * f_[2*j+3];
            rowE[i][4*j+2] = B * e_[2*j+1] + A * e_[2*j+2] + A * f_[2*j+2] + B * f_[2*j+3];
            rowE[i][4*j+3] = A * e_[2*j+1] + B * e_[2*j+2] + B * f_[2*j+3] + A * f_[2*j+4];
        }
    }
#pragma unroll
    for (int i = 0; i < 3; i++) {
        const __half2* oeP = (const __half2*)(OEp + (m + i) * 72 + k0 + 2);
        const __half2* ooP = (const __half2*)(OOp + (m + i) * 72 + k0);
        float2 a0 = __half22float2(oeP[0]);
        float2 a1 = __half22float2(oeP[1]);
        float2 a2 = __half22float2(oeP[2]);
        float2 c0 = __half22float2(ooP[0]);
        float2 c1 = __half22float2(ooP[1]);
        float2 c2 = __half22float2(ooP[2]);
        float2 c3 = __half22float2(ooP[3]);
        float e_[6] = {a0.x, a0.y, a1.x, a1.y, a2.x, a2.y};
        float f_[8] = {c0.x, c0.y, c1.x, c1.y, c2.x, c2.y, c3.x, c3.y};
#pragma unroll
        for (int j = 0; j < 2; j++) {
            rowO[i][4*j+0] = B * e_[2*j]   + A * e_[2*j+1] + A * f_[2*j+1] + B * f_[2*j+2];
            rowO[i][4*j+1] = A * e_[2*j]   + B * e_[2*j+1] + B * f_[2*j+2] + A * f_[2*j+3];
            rowO[i][4*j+2] = B * e_[2*j+1] + A * e_[2*j+2] + A * f_[2*j+2] + B * f_[2*j+3];
            rowO[i][4*j+3] = A * e_[2*j+1] + B * e_[2*j+2] + B * f_[2*j+3] + A * f_[2*j+4];
        }
    }

    float o0[8], o1[8];
#pragma unroll
    for (int c = 0; c < 8; c++) {
        o0[c] = B * rowE[0][c] + A * rowE[1][c] + A * rowO[0][c] + B * rowO[1][c] + bv;
        o1[c] = A * rowE[0][c] + B * rowE[1][c] + B * rowO[1][c] + A * rowO[2][c] + bv;
    }
    float* d0 = obase + (2 * m) * 128 + 2 * k0;
    float* d1 = obase + (2 * m + 1) * 128 + 2 * k0;
    *(float4*)(d0)     = make_float4(o0[0], o0[1], o0[2], o0[3]);
    *(float4*)(d0 + 4) = make_float4(o0[4], o0[5], o0[6], o0[7]);
    *(float4*)(d1)     = make_float4(o1[0], o1[1], o1[2], o1[3]);
    *(float4*)(d1 + 4) = make_float4(o1[4], o1[5], o1[6], o1[7]);
}

extern "C" void kernel_launch(void* const* d_in, const int* in_sizes, int n_in,
                              void* d_out, int out_size) {
    const float* hidden = (const float*)d_in[0];   // (8,256,64,64)
    const float* weight = (const float*)d_in[1];   // (256,256,3,3)
    const float* bias   = (const float*)d_in[2];   // (256,)
    float* out = (float*)d_out;                    // (8,256,128,128)

    cudaFuncSetAttribute(conv_s1_kernel,
                         cudaFuncAttributeMaxDynamicSharedMemorySize, 196608);

    prep_fused_kernel<<<2176, 512>>>(hidden, weight);
    conv_s1_kernel<<<dim3(34, 8, 4), 512, 196608>>>();
    blur_kernel<<<dim3(256, 8, 4), 256>>>(bias, out);
}

// round 16
// speedup vs baseline: 1.0714x; 1.0057x over previous
#include <cuda_runtime.h>
#include <cuda_fp16.h>
#include <cstdint>

// ============================================================================
// FirUpsample2D, two-stage minimal-FLOP formulation (single stream, R13 base).
// Stage 1 (tensor): y = convT(x, w, up=2, pad=2) as 4 parity-plane convs
//   (K = ntaps*256), y written FP16 into HALO-PADDED planes
//   g_Yp[n][plane][oc][68 x 72], interior cell (b,c) at (b+1, c+2).
//   Halo never written; __device__ globals zero-initialized -> zeros.
// Stage 2 (memory): parity blend [.25,.75]^2 + bias; thread = 2 rows x 8 cols.
// R15 delta vs R13: B fragments loaded via LDSM4 (nf-pairs), -25% shared ops.
// ============================================================================

#define CIN 256
#define OCH 256

__device__ __align__(16) __half g_W2[4 * 2 * 16 * 8192];
__device__ __align__(16) uint4 g_X8[8 * 32 * 4096];
__device__ __align__(16) __half g_Yp[8 * 4 * 256 * 4896];

__device__ __forceinline__ uint32_t swz(uint32_t o) { return o ^ ((o >> 3) & 0x70); }

__device__ __forceinline__ uint32_t smem_u32(const void* p) {
    uint32_t a;
    asm("{ .reg .u64 t; cvta.to.shared.u64 t, %1; cvt.u32.u64 %0, t; }" : "=r"(a) : "l"(p));
    return a;
}

#define CP16(d, s) asm volatile("cp.async.cg.shared.global [%0], [%1], 16;" :: "r"(d), "l"(s) : "memory")
#define CP16Z(d, s, z) asm volatile("cp.async.cg.shared.global [%0], [%1], 16, %2;" :: "r"(d), "l"(s), "r"(z) : "memory")
#define CP_COMMIT() asm volatile("cp.async.commit_group;" ::: "memory")
#define CP_WAIT1() asm volatile("cp.async.wait_group 1;" ::: "memory")
#define CP_WAIT0() asm volatile("cp.async.wait_group 0;" ::: "memory")

#define LDSM4(r, a) asm volatile( \
    "ldmatrix.sync.aligned.m8n8.x4.shared.b16 {%0,%1,%2,%3}, [%4];" \
    : "=r"((r)[0]), "=r"((r)[1]), "=r"((r)[2]), "=r"((r)[3]) : "r"(a))

#define MMA(c, a, b) asm volatile( \
    "mma.sync.aligned.m16n8k16.row.col.f32.f16.f16.f32 " \
    "{%0,%1,%2,%3},{%4,%5,%6,%7},{%8,%9},{%0,%1,%2,%3};" \
    : "+f"((c)[0]), "+f"((c)[1]), "+f"((c)[2]), "+f"((c)[3]) \
    : "r"((a)[0]), "r"((a)[1]), "r"((a)[2]), "r"((a)[3]), "r"((b)[0]), "r"((b)[1]))

// ---------------------------------------------------------------------------
// fused prep: blocks [0,2048) pack x -> c8 fp16; blocks [2048,2176) build
// per-plane fp16 weight images (2 oc per block).   (validated R13)
// ---------------------------------------------------------------------------
__global__ __launch_bounds__(512) void prep_fused_kernel(
    const float* __restrict__ x, const float* __restrict__ weight)
{
    if (blockIdx.x < 2048) {
        int idx = blockIdx.x * 512 + threadIdx.x;
        int hw = idx & 4095;
        int c8 = (idx >> 12) & 31;
        int n  = idx >> 17;
        const float* px = x + ((size_t)n * CIN + c8 * 8) * 4096 + hw;
        ushort h[8];
#pragma unroll
        for (int i = 0; i < 8; i++)
            h[i] = __half_as_ushort(__float2half_rn(px[i * 4096]));
        uint4 v;
        v.x = (uint32_t)h[0] | ((uint32_t)h[1] << 16);
        v.y = (uint32_t)h[2] | ((uint32_t)h[3] << 16);
        v.z = (uint32_t)h[4] | ((uint32_t)h[5] << 16);
        v.w = (uint32_t)h[6] | ((uint32_t)h[7] << 16);
        g_X8[idx] = v;
    } else {
        int b = blockIdx.x - 2048;             // 0..127
        int oc = b * 2 + (threadIdx.x >> 8);
        int ch = threadIdx.x & 255;
        float wv[3][3];
#pragma unroll
        for (int u = 0; u < 3; u++)
#pragma unroll
            for (int v = 0; v < 3; v++)
                wv[u][v] = weight[((oc * CIN + ch) * 3 + u) * 3 + v];

        int octile = oc >> 7, row = oc & 127;
        int q = ch >> 6, k = ch & 63;

        auto st = [&](int plane, int t, int u, int v) {
            int kc = t * 4 + q;
            size_t off = ((size_t)((plane * 2 + octile) * 16 + kc)) * 8192
                       + (size_t)row * 64 + k;
            g_W2[off] = __float2half_rn(wv[u][v]);
        };
        st(0, 0, 0, 0); st(0, 1, 0, 2); st(0, 2, 2, 0); st(0, 3, 2, 2);
        st(1, 0, 0, 1); st(1, 1, 2, 1);
        st(2, 0, 1, 0); st(2, 1, 1, 2);
        st(3, 0, 1, 1);
    }
}

// ---------------------------------------------------------------------------
// Stage 1: grid (34 tiles, 8 n, 4 planes), 512 threads, 192KB smem.
// CTA: M=256 oc x N=128 flat plane positions. MMA core validated (R6-R13);
// B loads fused to LDSM4 nf-pairs.
// ---------------------------------------------------------------------------
__global__ __launch_bounds__(512, 1) void conv_s1_kernel() {
    const int plane = blockIdx.z;
    const int n = blockIdx.y;
    const int tile = blockIdx.x;

    const int R = 65 - (plane >> 1);
    const int C = 65 - (plane & 1);
    const int npos = R * C;
    if (tile * 128 >= npos) return;
    const int nst = (plane == 0) ? 8 : ((plane == 3) ? 2 : 4);

    extern __shared__ char smem[];
    const uint32_t sb = smem_u32(smem);
    const int tid = threadIdx.x;
    const int warp = tid >> 5, lane = tid & 31;
    const int wm = warp & 3, wn = warp >> 2;

    float acc[4][4][4];
#pragma unroll
    for (int mf = 0; mf < 4; mf++)
#pragma unroll
        for (int nf = 0; nf < 4; nf++)
#pragma unroll
            for (int i = 0; i < 4; i++) acc[mf][nf][i] = 0.0f;

    // B prefetch geometry
    const int posT = tid & 127;
    const int selB = tid >> 7;
    const int kcuB = selB >> 1, hfB = selB & 1;
    const int pos = tile * 128 + posT;
    int bT, cT;
    if ((plane & 1) == 0) { bT = (int)(((unsigned)pos * 16133u) >> 20); cT = pos - bT * 65; }
    else                  { bT = pos >> 6; cT = pos & 63; }
    const int posOK = pos < npos;

    // ldmatrix geometry (validated A mapping; B re-derived for LDSM4 pairs)
    const int rowA0 = wm * 64 + (lane & 7) + ((lane >> 3) & 1) * 8;
    const int kbA = ((lane >> 4) & 1) * 16;
    // B LDSM4: lanes 0-7 -> (rowgrp 2p, k-lo), 8-15 -> (2p, k-hi),
    //          16-23 -> (2p+1, k-lo), 24-31 -> (2p+1, k-hi)
    const int rowB4 = wn * 32 + ((lane >> 4) & 1) * 8 + (lane & 7);
    const int kbB = ((lane >> 3) & 1) * 16;

#define PREFETCH(st, s) do {                                                        \
    uint32_t stg = sb + (uint32_t)(s) * 98304u;                                     \
    _Pragma("unroll")                                                               \
    for (int j = 0; j < 8; j++) {                                                   \
        uint32_t v = (uint32_t)(j * 512 + tid);                                     \
        uint32_t tile4 = v >> 10, idx = v & 1023;                                   \
        int kcu = tile4 >> 1, octile = tile4 & 1;                                   \
        const unsigned char* src = (const unsigned char*)g_W2                       \
            + ((size_t)((plane * 2 + octile) * 16 + (2 * (st) + kcu))) * 16384u     \
            + idx * 16u;                                                            \
        CP16(stg + tile4 * 16384u + swz(idx * 16u), src);                           \
    }                                                                               \
    {                                                                               \
        int kc = 2 * (st) + kcuB;                                                   \
        int t = kc >> 2, q = kc & 3;                                                \
        int gh, gw;                                                                 \
        if (plane == 0)      { gh = bT - 1 + (t >> 1); gw = cT - 1 + (t & 1); }     \
        else if (plane == 1) { gh = bT - 1 + t;        gw = cT; }                   \
        else if (plane == 2) { gh = bT;                gw = cT - 1 + t; }           \
        else                 { gh = bT;                gw = cT; }                   \
        int inb = ((unsigned)gh < 64u && (unsigned)gw < 64u && posOK) ? 16 : 0;     \
        uint32_t gidx = (uint32_t)((n * 32 + q * 8 + hfB * 4) * 4096)               \
                        + (inb ? (uint32_t)(gh * 64 + gw) : 0u);                    \
        uint32_t brow = stg + 65536u + (uint32_t)kcuB * 16384u;                     \
        uint32_t boff = (uint32_t)posT * 128u + (uint32_t)hfB * 64u;                \
        _Pragma("unroll")                                                           \
        for (int i = 0; i < 4; i++)                                                 \
            CP16Z(brow + swz(boff + (uint32_t)i * 16u),                             \
                  g_X8 + gidx + i * 4096, inb);                                     \
    }                                                                               \
} while (0)

    PREFETCH(0, 0);
    CP_COMMIT();

    for (int st = 0; st < nst; st++) {
        const int s = st & 1;
        if (st + 1 < nst) {
            PREFETCH(st + 1, s ^ 1);
            CP_COMMIT();
            CP_WAIT1();
        } else {
            CP_WAIT0();
        }
        __syncthreads();

        const uint32_t stg = sb + (uint32_t)s * 98304u;
#pragma unroll
        for (int kcu = 0; kcu < 2; kcu++) {
            const uint32_t A0 = stg + (uint32_t)kcu * 32768u;
            const uint32_t B0 = stg + 65536u + (uint32_t)kcu * 16384u;
#pragma unroll
            for (int ks = 0; ks < 4; ks++) {
                uint32_t a[4][4], b[4][2];
#pragma unroll
                for (int mf = 0; mf < 4; mf++) {
                    uint32_t ao = swz((uint32_t)(rowA0 + mf * 16) * 128u
                                      + (uint32_t)(ks * 32 + kbA));
                    LDSM4(a[mf], A0 + ao);
                }
#pragma unroll
                for (int p = 0; p < 2; p++) {
                    uint32_t tmp[4];
                    uint32_t bo = swz((uint32_t)(rowB4 + p * 16) * 128u
                                      + (uint32_t)(ks * 32 + kbB));
                    LDSM4(tmp, B0 + bo);
                    b[2 * p][0] = tmp[0]; b[2 * p][1] = tmp[1];
                    b[2 * p + 1][0] = tmp[2]; b[2 * p + 1][1] = tmp[3];
                }
#pragma unroll
                for (int mf = 0; mf < 4; mf++)
#pragma unroll
                    for (int nf = 0; nf < 4; nf++)
                        MMA(acc[mf][nf], a[mf], b[nf]);
            }
        }
        __syncthreads();
    }

    // ---- epilogue: write fp16 y into padded slices (halo untouched = zero)
    const int g = lane >> 2, tq = lane & 3;
    __half* ybase = g_Yp + (size_t)((n * 4 + plane) * 256) * 4896;
#pragma unroll
    for (int mf = 0; mf < 4; mf++) {
#pragma unroll
        for (int nf = 0; nf < 4; nf++) {
            int pos0 = tile * 128 + wn * 32 + nf * 8 + tq * 2;
            if (pos0 >= npos) continue;
            int oc0 = wm * 64 + mf * 16 + g;
            __half* s0 = ybase + (size_t)oc0 * 4896;
            __half* s1 = ybase + (size_t)(oc0 + 8) * 4896;
            int b, c;
            if ((plane & 1) == 0) { b = (int)(((unsigned)pos0 * 16133u) >> 20); c = pos0 - b * 65; }
            else                  { b = pos0 >> 6; c = pos0 & 63; }
            uint32_t o0 = (uint32_t)(b + 1) * 72u + (uint32_t)(c + 2);
            bool pair = (pos0 + 1 < npos);
            __half h0 = __float2half_rn(acc[mf][nf][0]);
            __half h1 = __float2half_rn(acc[mf][nf][1]);
            __half h2 = __float2half_rn(acc[mf][nf][2]);
            __half h3 = __float2half_rn(acc[mf][nf][3]);
            if (pair && c < C - 1) {
                if ((c & 1) == 0) {
                    *(__half2*)(s0 + o0) = __halves2half2(h0, h1);
                    *(__half2*)(s1 + o0) = __halves2half2(h2, h3);
                } else {
                    s0[o0] = h0; s0[o0 + 1] = h1;
                    s1[o0] = h2; s1[o0 + 1] = h3;
                }
            } else {
                s0[o0] = h0;
                s1[o0] = h2;
                if (pair) {          // row straddle (odd-width plane, c == C-1)
                    uint32_t o1 = (uint32_t)(b + 2) * 72u + 2u;
                    s0[o1] = h1;
                    s1[o1] = h3;
                }
            }
        }
    }
}

// ---------------------------------------------------------------------------
// Stage 2: FIR parity blend + bias. Thread -> 2 rows x 8 out cols (two k-pairs,
// k0 = 4*kg even => all half2 loads aligned). grid (256 oc, 8 n, 4), 256 thr.
// (validated R13)
// ---------------------------------------------------------------------------
__global__ __launch_bounds__(256) void blur_kernel(
    const float* __restrict__ bias, float* __restrict__ out)
{
    const int oc = blockIdx.x, n = blockIdx.y, rg = blockIdx.z;
    const int tid = threadIdx.x;
    const __half* EEp = g_Yp + ((size_t)(n * 4 + 0) * 256 + oc) * 4896;
    const __half* EOp = g_Yp + ((size_t)(n * 4 + 1) * 256 + oc) * 4896;
    const __half* OEp = g_Yp + ((size_t)(n * 4 + 2) * 256 + oc) * 4896;
    const __half* OOp = g_Yp + ((size_t)(n * 4 + 3) * 256 + oc) * 4896;
    const float bv = bias[oc];
    float* obase = out + (size_t)(n * 256 + oc) * 16384;

    const float A = 0.25f, B = 0.75f;
    int id = rg * 256 + tid;              // 0..1023
    int m = id >> 4, kg = id & 15;
    int k0 = kg * 4;                      // even y-column base, 2 pairs

    float rowE[2][8], rowO[3][8];
#pragma unroll
    for (int i = 0; i < 2; i++) {
        const __half2* eeP = (const __half2*)(EEp + (m + 1 + i) * 72 + k0 + 2);
        const __half2* eoP = (const __half2*)(EOp + (m + 1 + i) * 72 + k0);
        float2 a0 = __half22float2(eeP[0]);
        float2 a1 = __half22float2(eeP[1]);
        float2 a2 = __half22float2(eeP[2]);
        float2 c0 = __half22float2(eoP[0]);
        float2 c1 = __half22float2(eoP[1]);
        float2 c2 = __half22float2(eoP[2]);
        float2 c3 = __half22float2(eoP[3]);
        float e_[6] = {a0.x, a0.y, a1.x, a1.y, a2.x, a2.y};
        float f_[8] = {c0.x, c0.y, c1.x, c1.y, c2.x, c2.y, c3.x, c3.y};
#pragma unroll
        for (int j = 0; j < 2; j++) {
            rowE[i][4*j+0] = B * e_[2*j]   + A * e_[2*j+1] + A * f_[2*j+1] + B * f_[2*j+2];
            rowE[i][4*j+1] = A * e_[2*j]   + B * e_[2*j+1] + B * f_[2*j+2] + A * f_[2*j+3];
            rowE[i][4*j+2] = B * e_[2*j+1] + A * e_[2*j+2] + A * f_[2*j+2] + B * f_[2*j+3];
            rowE[i][4*j+3] = A * e_[2*j+1] + B * e_[2*j+2] + B * f_[2*j+3] + A * f_[2*j+4];
        }
    }
#pragma unroll
    for (int i = 0; i < 3; i++) {
        const __half2* oeP = (const __half2*)(OEp + (m + i) * 72 + k0 + 2);
        const __half2* ooP = (const __half2*)(OOp + (m + i) * 72 + k0);
        float2 a0 = __half22float2(oeP[0]);
        float2 a1 = __half22float2(oeP[1]);
        float2 a2 = __half22float2(oeP[2]);
        float2 c0 = __half22float2(ooP[0]);
        float2 c1 = __half22float2(ooP[1]);
        float2 c2 = __half22float2(ooP[2]);
        float2 c3 = __half22float2(ooP[3]);
        float e_[6] = {a0.x, a0.y, a1.x, a1.y, a2.x, a2.y};
        float f_[8] = {c0.x, c0.y, c1.x, c1.y, c2.x, c2.y, c3.x, c3.y};
#pragma unroll
        for (int j = 0; j < 2; j++) {
            rowO[i][4*j+0] = B * e_[2*j]   + A * e_[2*j+1] + A * f_[2*j+1] + B * f_[2*j+2];
            rowO[i][4*j+1] = A * e_[2*j]   + B * e_[2*j+1] + B * f_[2*j+2] + A * f_[2*j+3];
            rowO[i][4*j+2] = B * e_[2*j+1] + A * e_[2*j+2] + A * f_[2*j+2] + B * f_[2*j+3];
            rowO[i][4*j+3] = A * e_[2*j+1] + B * e_[2*j+2] + B * f_[2*j+3] + A * f_[2*j+4];
        }
    }

    float o0[8], o1[8];
#pragma unroll
    for (int c = 0; c < 8; c++) {
        o0[c] = B * rowE[0][c] + A * rowE[1][c] + A * rowO[0][c] + B * rowO[1][c] + bv;
        o1[c] = A * rowE[0][c] + B * rowE[1][c] + B * rowO[1][c] + A * rowO[2][c] + bv;
    }
    float* d0 = obase + (2 * m) * 128 + 2 * k0;
    float* d1 = obase + (2 * m + 1) * 128 + 2 * k0;
    *(float4*)(d0)     = make_float4(o0[0], o0[1], o0[2], o0[3]);
    *(float4*)(d0 + 4) = make_float4(o0[4], o0[5], o0[6], o0[7]);
    *(float4*)(d1)     = make_float4(o1[0], o1[1], o1[2], o1[3]);
    *(float4*)(d1 + 4) = make_float4(o1[4], o1[5], o1[6], o1[7]);
}

extern "C" void kernel_launch(void* const* d_in, const int* in_sizes, int n_in,
                              void* d_out, int out_size) {
    const float* hidden = (const float*)d_in[0];   // (8,256,64,64)
    const float* weight = (const float*)d_in[1];   // (256,256,3,3)
    const float* bias   = (const float*)d_in[2];   // (256,)
    float* out = (float*)d_out;                    // (8,256,128,128)

    cudaFuncSetAttribute(conv_s1_kernel,
                         cudaFuncAttributeMaxDynamicSharedMemorySize, 196608);

    prep_fused_kernel<<<2176, 512>>>(hidden, weight);
    conv_s1_kernel<<<dim3(34, 8, 4), 512, 196608>>>();
    blur_kernel<<<dim3(256, 8, 4), 256>>>(bias, out);
}